// round 11
// baseline (speedup 1.0000x reference)
#include <cuda_runtime.h>
#include <cstdint>

// Problem constants
#define Bn 32
#define Dn 1024
#define Hn 1024
#define BETA 0.9f

// Output layout (reference return order):
//   [0, B*H)              out   = tanh(a)
//   [B*H, 2*B*H)          u_new = a
//   [2*B*H, +B*D*H)       E_w_new = 0.9*E_w + x[i,d]  (broadcast over h)
//   [..., +B*H)           E_b_new = 0.9*E_b + 1
// a[i,h] = 0.9*u[i,h] + sum_d x[i,d]*w[d,h] + b[h]

#define NB_STREAM 168          // pure-stream blocks (bid 0..167)
#define NB_GEMM   128          // GEMM-then-stream blocks (bid 168..295)
#define NB_TOTAL  (NB_STREAM + NB_GEMM)   // 296 = 148 SMs * 2 blocks: ONE wave
#define NWARPS_T  (NB_TOTAL * 8)          // 2368 warps share the stream
#define ROWS      (Bn * Dn)               // 32768 rows of H=1024 floats
#define OFF_UNEW (Bn*Hn)
#define OFF_EW   (2*Bn*Hn)
#define OFF_EB   (2*Bn*Hn + Bn*Dn*Hn)

// row r: float4 index r*256 + k*32 + lane, k=0..7
#define LOADB(arr, r)                                                   \
    do { const float4* _s = e4 + (size_t)(r) * 256 + lane;              \
         _Pragma("unroll")                                              \
         for (int _k = 0; _k < 8; ++_k) arr[_k] = __ldcs(_s + _k * 32); \
    } while (0)

#define STOREB(arr, r, xv)                                              \
    do { float4* _o = o4 + (size_t)(r) * 256 + lane;                    \
         _Pragma("unroll")                                              \
         for (int _k = 0; _k < 8; ++_k) {                               \
             float4 _v;                                                 \
             _v.x = fmaf(BETA, arr[_k].x, xv);                          \
             _v.y = fmaf(BETA, arr[_k].y, xv);                          \
             _v.z = fmaf(BETA, arr[_k].z, xv);                          \
             _v.w = fmaf(BETA, arr[_k].w, xv);                          \
             __stcs(_o + _k * 32, _v);                                  \
         }                                                              \
    } while (0)

__global__ void __launch_bounds__(256)
diag_rtrl_kernel(const float* __restrict__ x,
                 const float* __restrict__ w,
                 const float* __restrict__ b,
                 const float* __restrict__ u,
                 const float* __restrict__ E_w,
                 const float* __restrict__ E_b,
                 float* __restrict__ out)
{
    __shared__ float xs[Dn];   // GEMM phase only (4 KB)

    const int bid  = blockIdx.x;
    const int t    = threadIdx.x;
    const int lane = t & 31;

    int W;   // global stream-warp id; stream-only blocks get low ids (extra rows)

    if (bid >= NB_STREAM) {
        // ---- GEMM + tanh + u_new + E_b prologue, then fall through ----
        const int gb    = bid - NB_STREAM;
        const int i     = gb >> 2;           // batch row
        const int hbase = (gb & 3) * 256;    // h chunk

        const float4* xr = reinterpret_cast<const float4*>(x + i * Dn);
        reinterpret_cast<float4*>(xs)[t] = xr[t];
        __syncthreads();

        const int h = hbase + t;
        const float* wc = w + h;
        float acc = 0.0f;
        #pragma unroll 16
        for (int d = 0; d < Dn; ++d) {
            acc = fmaf(xs[d], __ldg(wc + d * Hn), acc);
        }

        const int ih = i * Hn + h;
        const float a = fmaf(BETA, u[ih], acc + b[h]);
        out[ih]            = tanhf(a);
        out[OFF_UNEW + ih] = a;
        out[OFF_EB   + ih] = fmaf(BETA, E_b[ih], 1.0f);

        W = NB_STREAM * 8 + gb * 8 + (t >> 5);
    } else {
        W = bid * 8 + (t >> 5);
    }

    // ---- E_w streaming: full-row depth-2 ping-pong (8 f4 outstanding) ----
    const int n = (ROWS - 1 - W) / NWARPS_T + 1;   // 13 or 14 rows

    const float4* e4 = reinterpret_cast<const float4*>(E_w);
    float4*       o4 = reinterpret_cast<float4*>(out + OFF_EW);

    float4 A[8], Bv[8];
    size_t r  = (size_t)W;
    float  xA = __ldg(x + r);
    LOADB(A, r);

    size_t rp = r;          // row pending in the active buffer
    float  xB;
    bool   pa = true;       // pending buffer is A?

    for (int i = 1; i < n; ++i) {
        const size_t rn = (size_t)W + (size_t)i * NWARPS_T;
        if (pa) {
            xB = __ldg(x + rn);
            LOADB(Bv, rn);          // next row's 8 loads in flight...
            STOREB(A, rp, xA);      // ...while draining previous row
        } else {
            xA = __ldg(x + rn);
            LOADB(A, rn);
            STOREB(Bv, rp, xB);
        }
        rp = rn;
        pa = !pa;
    }
    if (pa) { STOREB(A, rp, xA); } else { STOREB(Bv, rp, xB); }
}

extern "C" void kernel_launch(void* const* d_in, const int* in_sizes, int n_in,
                              void* d_out, int out_size)
{
    const float* x   = (const float*)d_in[0];   // [32,1024]
    const float* w   = (const float*)d_in[1];   // [1024,1024]
    const float* b   = (const float*)d_in[2];   // [1024]
    const float* u   = (const float*)d_in[3];   // [32,1024]
    const float* E_w = (const float*)d_in[4];   // [1,32,1024,1024]
    const float* E_b = (const float*)d_in[5];   // [1,32,1024]
    float* out = (float*)d_out;

    diag_rtrl_kernel<<<NB_TOTAL, 256>>>(x, w, b, u, E_w, E_b, out);
}

// round 12
// speedup vs baseline: 1.1596x; 1.1596x over previous
#include <cuda_runtime.h>
#include <cstdint>

// Problem constants
#define Bn 32
#define Dn 1024
#define Hn 1024
#define BETA 0.9f

// Output layout (reference return order):
//   [0, B*H)              out   = tanh(a)
//   [B*H, 2*B*H)          u_new = a
//   [2*B*H, +B*D*H)       E_w_new = 0.9*E_w + x[i,d]  (broadcast over h)
//   [..., +B*H)           E_b_new = 0.9*E_b + 1
// a[i,h] = 0.9*u[i,h] + sum_d x[i,d]*w[d,h] + b[h]

#define NB_GEMM 128          // 32 i-rows * 4 h-chunks of 256 (short blocks)
#define NB_EW   464          // stream blocks; total 592 = 2 full waves @2/SM
#define NWARPS  (NB_EW * 8)  // 3712 stream warps
#define ROWS    (Bn * Dn)    // 32768 rows of H=1024 floats
#define OFF_UNEW (Bn*Hn)
#define OFF_EW   (2*Bn*Hn)
#define OFF_EB   (2*Bn*Hn + Bn*Dn*Hn)

// row r: float4 index r*256 + k*32 + lane, k=0..7
#define LOADB(arr, r)                                                   \
    do { const float4* _s = e4 + (size_t)(r) * 256 + lane;              \
         _Pragma("unroll")                                              \
         for (int _k = 0; _k < 8; ++_k) arr[_k] = __ldcs(_s + _k * 32); \
    } while (0)

#define STOREB(arr, r, xv)                                              \
    do { float4* _o = o4 + (size_t)(r) * 256 + lane;                    \
         _Pragma("unroll")                                              \
         for (int _k = 0; _k < 8; ++_k) {                               \
             float4 _v;                                                 \
             _v.x = fmaf(BETA, arr[_k].x, xv);                          \
             _v.y = fmaf(BETA, arr[_k].y, xv);                          \
             _v.z = fmaf(BETA, arr[_k].z, xv);                          \
             _v.w = fmaf(BETA, arr[_k].w, xv);                          \
             __stcs(_o + _k * 32, _v);                                  \
         }                                                              \
    } while (0)

__global__ void __launch_bounds__(256)
diag_rtrl_kernel(const float* __restrict__ x,
                 const float* __restrict__ w,
                 const float* __restrict__ b,
                 const float* __restrict__ u,
                 const float* __restrict__ E_w,
                 const float* __restrict__ E_b,
                 float* __restrict__ out)
{
    __shared__ float xs[Dn];   // GEMM path only (4 KB)

    const int bid = blockIdx.x;
    const int t   = threadIdx.x;

    if (bid < NB_GEMM) {
        // ---- GEMM + tanh + u_new + E_b path (short block, exits early) ----
        const int i     = bid >> 2;          // batch row
        const int hbase = (bid & 3) * 256;   // h chunk

        const float4* xr = reinterpret_cast<const float4*>(x + i * Dn);
        reinterpret_cast<float4*>(xs)[t] = xr[t];
        __syncthreads();

        const int h = hbase + t;
        const float* wc = w + h;
        float acc = 0.0f;
        #pragma unroll 16
        for (int d = 0; d < Dn; ++d) {
            acc = fmaf(xs[d], __ldg(wc + d * Hn), acc);
        }

        const int ih = i * Hn + h;
        const float a = fmaf(BETA, u[ih], acc + b[h]);
        out[ih]            = tanhf(a);
        out[OFF_UNEW + ih] = a;
        out[OFF_EB   + ih] = fmaf(BETA, E_b[ih], 1.0f);
        return;
    }

    // ---- E_w streaming: persistent warps, full-row depth-2 ping-pong ----
    const int lane = t & 31;
    const int W    = (bid - NB_GEMM) * 8 + (t >> 5);   // stream warp id
    const int n    = (ROWS - 1 - W) / NWARPS + 1;      // 8 or 9 rows

    const float4* e4 = reinterpret_cast<const float4*>(E_w);
    float4*       o4 = reinterpret_cast<float4*>(out + OFF_EW);

    float4 A[8], Bv[8];
    size_t r  = (size_t)W;
    float  xA = __ldg(x + r);
    LOADB(A, r);

    size_t rp = r;          // row pending in the active buffer
    float  xB;
    bool   pa = true;       // pending buffer is A?

    for (int i = 1; i < n; ++i) {
        const size_t rn = (size_t)W + (size_t)i * NWARPS;
        if (pa) {
            xB = __ldg(x + rn);
            LOADB(Bv, rn);          // next row's 8 loads in flight...
            STOREB(A, rp, xA);      // ...while draining previous row
        } else {
            xA = __ldg(x + rn);
            LOADB(A, rn);
            STOREB(Bv, rp, xB);
        }
        rp = rn;
        pa = !pa;
    }
    if (pa) { STOREB(A, rp, xA); } else { STOREB(Bv, rp, xB); }
}

extern "C" void kernel_launch(void* const* d_in, const int* in_sizes, int n_in,
                              void* d_out, int out_size)
{
    const float* x   = (const float*)d_in[0];   // [32,1024]
    const float* w   = (const float*)d_in[1];   // [1024,1024]
    const float* b   = (const float*)d_in[2];   // [1024]
    const float* u   = (const float*)d_in[3];   // [32,1024]
    const float* E_w = (const float*)d_in[4];   // [1,32,1024,1024]
    const float* E_b = (const float*)d_in[5];   // [1,32,1024]
    float* out = (float*)d_out;

    diag_rtrl_kernel<<<NB_GEMM + NB_EW, 256>>>(x, w, b, u, E_w, E_b, out);
}